// round 5
// baseline (speedup 1.0000x reference)
#include <cuda_runtime.h>

// ---------------------------------------------------------------------------
// WindowGrapherPyg fused kernel, R4: warp tile 8x96, k-paired f32x2 GEMMs.
// One CTA (512 thr) per 8x8 window; xw/Q/K/V resident in smem.
// GEMM decomposition: 16 warps = 8 row-groups x 2 col-groups.
//   thread: 8 rows x 3 cols, accumulators k-paired (even/odd partials in f32x2,
//   horizontal add at epilogue). A loads broadcast LDS.128; B conflict-free
//   scalar LDS; bias added at epilogue.
// ---------------------------------------------------------------------------

typedef unsigned long long u64;

namespace {
constexpr int Bc = 2, Cc = 192, Hc = 192, Wc = 192;
constexpr int WS = 8, NN = 64, KK = 9, HEADS = 8, DH = 24;
constexpr int NWH = Hc / WS, NWW = Wc / WS;         // 24 x 24
constexpr int WB = Bc * NWH * NWW;                  // 1152 windows
constexpr int STR = 196;                            // padded row stride
constexpr int NT = 512;
constexpr int XW_FLOATS = NN * STR;                 // 12544
constexpr int WT_FLOATS = 32 * Cc;                  // 6144 (aliases Gram 64*64)
constexpr size_t SMEM_BYTES =
    (size_t)(4 * XW_FLOATS + WT_FLOATS + NN) * sizeof(float) +
    (size_t)(NN * KK) * sizeof(int);                // 227,840 B
constexpr float INV_SQRT_DH = 0.20412414523193154f;
}

__device__ __forceinline__ u64 pack2f(float x, float y) {
  u64 r; asm("mov.b64 %0, {%1, %2};" : "=l"(r) : "f"(x), "f"(y)); return r;
}
__device__ __forceinline__ void fma2(u64& d, u64 a, u64 b) {
  asm("fma.rn.f32x2 %0, %1, %2, %0;" : "+l"(d) : "l"(a), "l"(b));
}
__device__ __forceinline__ float2 unpack2(u64 v) {
  float2 o; asm("mov.b64 {%0, %1}, %2;" : "=f"(o.x), "=f"(o.y) : "l"(v));
  return o;
}
__device__ __forceinline__ float hsum2(u64 v) {
  float2 o = unpack2(v); return o.x + o.y;
}

// acc[8][3]: rows rg*8+r, cols tx + 32j + 96cg. k-paired partial sums.
__device__ __forceinline__ void gemm_core(const float* __restrict__ sXW,
                                          const float* __restrict__ Wg,
                                          float* __restrict__ sWT,
                                          u64 acc[8][3], int tid) {
  const int warp = tid >> 5, tx = tid & 31;
  const int rg = warp >> 1, cg = warp & 1;
  const int c0 = tx + 96 * cg;
#pragma unroll
  for (int r = 0; r < 8; r++)
#pragma unroll
    for (int j = 0; j < 3; j++) acc[r][j] = 0ull;

  float4 pf[3];
#pragma unroll
  for (int i = 0; i < 3; i++) {
    int t = tid + NT * i, kr = t / 48, cq = t - kr * 48;
    pf[i] = *(const float4*)(Wg + kr * Cc + cq * 4);
  }
  const float* arow = sXW + rg * 8 * STR;
  for (int ko = 0; ko < Cc; ko += 32) {
    __syncthreads();  // prior consumers of sWT done
#pragma unroll
    for (int i = 0; i < 3; i++) {
      int t = tid + NT * i, kr = t / 48, cq = t - kr * 48;
      *(float4*)(sWT + kr * Cc + cq * 4) = pf[i];
    }
    __syncthreads();
    if (ko + 32 < Cc) {  // prefetch next W tile under compute
#pragma unroll
      for (int i = 0; i < 3; i++) {
        int t = tid + NT * i, kr = t / 48, cq = t - kr * 48;
        pf[i] = *(const float4*)(Wg + (ko + 32 + kr) * Cc + cq * 4);
      }
    }
#pragma unroll
    for (int kq = 0; kq < 8; kq++) {
      float4 a4[8];
#pragma unroll
      for (int r = 0; r < 8; r++)
        a4[r] = *(const float4*)(arow + r * STR + ko + kq * 4);
      const float* wk = sWT + (kq * 4) * Cc + c0;
#pragma unroll
      for (int half = 0; half < 2; half++) {
        u64 b2[3];
#pragma unroll
        for (int j = 0; j < 3; j++)
          b2[j] = pack2f(wk[(2 * half) * Cc + 32 * j],
                         wk[(2 * half + 1) * Cc + 32 * j]);
#pragma unroll
        for (int r = 0; r < 8; r++) {
          u64 a2 = half ? pack2f(a4[r].z, a4[r].w) : pack2f(a4[r].x, a4[r].y);
#pragma unroll
          for (int j = 0; j < 3; j++) fma2(acc[r][j], a2, b2[j]);
        }
      }
    }
  }
}

__device__ __forceinline__ void gemm_to_smem(const float* __restrict__ sXW,
                                             const float* __restrict__ Wg,
                                             const float* __restrict__ bias,
                                             float* __restrict__ sWT,
                                             float* __restrict__ dst, int tid) {
  u64 acc[8][3];
  gemm_core(sXW, Wg, sWT, acc, tid);
  const int warp = tid >> 5, tx = tid & 31;
  const int rg = warp >> 1, cg = warp & 1;
#pragma unroll
  for (int j = 0; j < 3; j++) {
    const int c = tx + 96 * cg + 32 * j;
    const float bj = __ldg(bias + c);
#pragma unroll
    for (int r = 0; r < 8; r++)
      dst[(rg * 8 + r) * STR + c] = hsum2(acc[r][j]) + bj;
  }
  // no trailing sync: next consumer's first __syncthreads orders these stores
}

__device__ __forceinline__ void gemm_skip_out(const float* __restrict__ sXW,
                                              const float* __restrict__ Wg,
                                              const float* __restrict__ bias,
                                              float* __restrict__ sWT,
                                              const float* __restrict__ sAttn,
                                              float* __restrict__ out,
                                              int b, int h0, int w0, int tid) {
  u64 acc[8][3];
  gemm_core(sXW, Wg, sWT, acc, tid);
  const int warp = tid >> 5, tx = tid & 31;
  const int rg = warp >> 1, cg = warp & 1;
#pragma unroll
  for (int j = 0; j < 3; j++) {
    const int c = tx + 96 * cg + 32 * j;
    const float bj = __ldg(bias + c);
    float v[8];
#pragma unroll
    for (int r = 0; r < 8; r++)
      v[r] = hsum2(acc[r][j]) + bj + sAttn[(rg * 8 + r) * STR + c];
    float* d0 = out + ((b * Cc + c) * Hc + h0 + rg) * Wc + w0;
    *(float4*)d0 = make_float4(v[0], v[1], v[2], v[3]);
    *(float4*)(d0 + 4) = make_float4(v[4], v[5], v[6], v[7]);
  }
}

__global__ void __launch_bounds__(NT, 1)
wg_kernel(const float* __restrict__ x,
          const float* __restrict__ Wq, const float* __restrict__ bq,
          const float* __restrict__ Wk, const float* __restrict__ bk,
          const float* __restrict__ Wvw, const float* __restrict__ bv,
          const float* __restrict__ Wsk, const float* __restrict__ bsk,
          float* __restrict__ out) {
  extern __shared__ float sm[];
  float* sXW = sm;
  float* sQ = sXW + XW_FLOATS;
  float* sK = sQ + XW_FLOATS;
  float* sV = sK + XW_FLOATS;
  float* sWT = sV + XW_FLOATS;   // 6144 floats; first 4096 alias Gram
  float* sG = sWT;
  float* sSq = sWT + WT_FLOATS;  // 64 floats
  int* sIdx = (int*)(sSq + NN);  // 64*9 ints

  const int tid = threadIdx.x;
  const int w = blockIdx.x;
  const int b = w / (NWH * NWW);
  const int rem = w - b * (NWH * NWW);
  const int wh = rem / NWW, ww = rem - wh * NWW;
  const int h0 = wh * WS, w0 = ww * WS;

  // ---- Phase A: gather window nodes ----
#pragma unroll
  for (int i = 0; i < 3; i++) {
    int t = tid + NT * i;          // 0..1535 : (c, nh)
    int c = t >> 3, nh = t & 7;
    const float* src = x + ((b * Cc + c) * Hc + h0 + nh) * Wc + w0;
    float4 v0 = *(const float4*)src;
    float4 v1 = *(const float4*)(src + 4);
    float* d = sXW + (nh * 8) * STR + c;
    d[0 * STR] = v0.x; d[1 * STR] = v0.y; d[2 * STR] = v0.z; d[3 * STR] = v0.w;
    d[4 * STR] = v1.x; d[5 * STR] = v1.y; d[6 * STR] = v1.z; d[7 * STR] = v1.w;
  }
  __syncthreads();

  // ---- Phase B1: Gram matrix, all 512 threads, 1 row x 8 cols per thread ----
  {
    const int tn = tid >> 3;        // 0..63 (row)
    const int tm8 = tid & 7;        // cols tm8 + 8j
    u64 acc2[8];
#pragma unroll
    for (int j = 0; j < 8; j++) acc2[j] = 0ull;
    const float* ar = sXW + tn * STR;
#pragma unroll 2
    for (int k = 0; k < Cc; k += 4) {
      float4 a = *(const float4*)(ar + k);
      u64 alo = pack2f(a.x, a.y), ahi = pack2f(a.z, a.w);
#pragma unroll
      for (int j = 0; j < 8; j++) {
        float4 bb = *(const float4*)(sXW + (tm8 + 8 * j) * STR + k);
        fma2(acc2[j], alo, pack2f(bb.x, bb.y));
        fma2(acc2[j], ahi, pack2f(bb.z, bb.w));
      }
    }
#pragma unroll
    for (int j = 0; j < 8; j++)
      sG[tn * NN + tm8 + 8 * j] = hsum2(acc2[j]);
  }
  __syncthreads();
  if (tid < NN) sSq[tid] = sG[tid * (NN + 1)];
  __syncthreads();

  // ---- Phase B2: top-9 nearest neighbors (stable, exact fp32) ----
  if (tid < NN) {
    const int n = tid;
    unsigned long long mask = 1ull << n;  // exclude self
    const float sqn = sSq[n];
    const float* grow = sG + n * NN;
#pragma unroll 1
    for (int kk = 0; kk < KK; kk++) {
      float best = 3.0e38f;
      int bi = 0;
#pragma unroll 4
      for (int m = 0; m < NN; m++) {
        float d = sqn + sSq[m] - 2.0f * grow[m];
        if ((mask >> m) & 1ull) d = 3.9e38f;
        if (d < best) { best = d; bi = m; }  // '<' = lowest index wins ties
      }
      mask |= 1ull << bi;
      sIdx[n * KK + kk] = bi;
    }
  }
  __syncthreads();

  // ---- Phase C: Q, K, V projections ----
  gemm_to_smem(sXW, Wq, bq, sWT, sQ, tid);
  gemm_to_smem(sXW, Wk, bk, sWT, sK, tid);
  gemm_to_smem(sXW, Wvw, bv, sWT, sV, tid);
  __syncthreads();  // sQ/sK/sV visible to all before attention

  // ---- Phase D: 9-neighbor softmax attention; 512 thr = one (n,h) each ----
  {
    const int n = tid & (NN - 1);
    const int h = tid >> 6;
    const float* qp = sQ + n * STR + h * DH;
    float q[DH];
#pragma unroll
    for (int d4 = 0; d4 < DH / 4; d4++) {
      float4 v = *(const float4*)(qp + d4 * 4);
      q[d4 * 4 + 0] = v.x; q[d4 * 4 + 1] = v.y;
      q[d4 * 4 + 2] = v.z; q[d4 * 4 + 3] = v.w;
    }
    float sc[KK];
    int nb[KK];
#pragma unroll
    for (int kk = 0; kk < KK; kk++) {
      int m = sIdx[n * KK + kk];
      nb[kk] = m;
      const float* kp = sK + m * STR + h * DH;
      float s = 0.0f;
#pragma unroll
      for (int d4 = 0; d4 < DH / 4; d4++) {
        float4 v = *(const float4*)(kp + d4 * 4);
        s = fmaf(q[d4 * 4 + 0], v.x, s);
        s = fmaf(q[d4 * 4 + 1], v.y, s);
        s = fmaf(q[d4 * 4 + 2], v.z, s);
        s = fmaf(q[d4 * 4 + 3], v.w, s);
      }
      sc[kk] = s * INV_SQRT_DH;
    }
    float mx = sc[0];
#pragma unroll
    for (int kk = 1; kk < KK; kk++) mx = fmaxf(mx, sc[kk]);
    float ssum = 0.0f;
#pragma unroll
    for (int kk = 0; kk < KK; kk++) { sc[kk] = __expf(sc[kk] - mx); ssum += sc[kk]; }
    const float inv = 1.0f / ssum;
    float o[DH] = {};
#pragma unroll
    for (int kk = 0; kk < KK; kk++) {
      float a = sc[kk] * inv;
      const float* vp = sV + nb[kk] * STR + h * DH;
#pragma unroll
      for (int d4 = 0; d4 < DH / 4; d4++) {
        float4 v = *(const float4*)(vp + d4 * 4);
        o[d4 * 4 + 0] = fmaf(a, v.x, o[d4 * 4 + 0]);
        o[d4 * 4 + 1] = fmaf(a, v.y, o[d4 * 4 + 1]);
        o[d4 * 4 + 2] = fmaf(a, v.z, o[d4 * 4 + 2]);
        o[d4 * 4 + 3] = fmaf(a, v.w, o[d4 * 4 + 3]);
      }
    }
    float* op = sQ + n * STR + h * DH;  // attn out overwrites own q segment
#pragma unroll
    for (int d4 = 0; d4 < DH / 4; d4++)
      *(float4*)(op + d4 * 4) =
          make_float4(o[d4 * 4 + 0], o[d4 * 4 + 1], o[d4 * 4 + 2], o[d4 * 4 + 3]);
  }
  // first __syncthreads inside gemm_skip_out guards sQ (attn) reads

  // ---- Phase E: skip GEMM + attn add + scatter to [B,C,H,W] ----
  gemm_skip_out(sXW, Wsk, bsk, sWT, sQ, out, b, h0, w0, tid);
}

extern "C" void kernel_launch(void* const* d_in, const int* in_sizes, int n_in,
                              void* d_out, int out_size) {
  const float* x   = (const float*)d_in[0];
  const float* Wq  = (const float*)d_in[1];
  const float* bq  = (const float*)d_in[2];
  const float* Wk  = (const float*)d_in[3];
  const float* bk  = (const float*)d_in[4];
  const float* Wv  = (const float*)d_in[5];
  const float* bv  = (const float*)d_in[6];
  const float* Wsk = (const float*)d_in[7];
  const float* bsk = (const float*)d_in[8];
  float* out = (float*)d_out;

  cudaFuncSetAttribute(wg_kernel, cudaFuncAttributeMaxDynamicSharedMemorySize,
                       (int)SMEM_BYTES);
  wg_kernel<<<WB, NT, SMEM_BYTES>>>(x, Wq, bq, Wk, bk, Wv, bv, Wsk, bsk, out);
}

// round 6
// speedup vs baseline: 1.0077x; 1.0077x over previous
#include <cuda_runtime.h>

// ---------------------------------------------------------------------------
// WindowGrapherPyg fused kernel, R5: 768 threads (24 warps), 8 rg x 3 cg,
// thread tile 8 rows x 1 col-pair, f32x2 GEMMs, light register footprint.
// ---------------------------------------------------------------------------

typedef unsigned long long u64;

namespace {
constexpr int Bc = 2, Cc = 192, Hc = 192, Wc = 192;
constexpr int WS = 8, NN = 64, KK = 9, HEADS = 8, DH = 24;
constexpr int NWH = Hc / WS, NWW = Wc / WS;         // 24 x 24
constexpr int WB = Bc * NWH * NWW;                  // 1152 windows
constexpr int STR = 196;                            // padded row stride
constexpr int NT = 768;
constexpr int XW_FLOATS = NN * STR;                 // 12544
constexpr int WT_FLOATS = 32 * Cc;                  // 6144 (aliases Gram 64*64)
constexpr size_t SMEM_BYTES =
    (size_t)(4 * XW_FLOATS + WT_FLOATS + NN) * sizeof(float) +
    (size_t)(NN * KK) * sizeof(int);                // 227,840 B
constexpr float INV_SQRT_DH = 0.20412414523193154f;
}

__device__ __forceinline__ u64 dup2f(float a) {
  u64 r; asm("mov.b64 %0, {%1, %1};" : "=l"(r) : "f"(a)); return r;
}
__device__ __forceinline__ u64 pack2f(float x, float y) {
  u64 r; asm("mov.b64 %0, {%1, %2};" : "=l"(r) : "f"(x), "f"(y)); return r;
}
__device__ __forceinline__ void fma2(u64& d, u64 a, u64 b) {
  asm("fma.rn.f32x2 %0, %1, %2, %0;" : "+l"(d) : "l"(a), "l"(b));
}
__device__ __forceinline__ float2 unpack2(u64 v) {
  float2 o; asm("mov.b64 {%0, %1}, %2;" : "=f"(o.x), "=f"(o.y) : "l"(v));
  return o;
}
__device__ __forceinline__ float hsum2(u64 v) {
  float2 o = unpack2(v); return o.x + o.y;
}

// 24 warps: rg = warp>>... warp = rg*3 + cg (rg 0..7, cg 0..2).
// Thread: rows rg*8..rg*8+7, cols (2*tx + 64*cg, +1). acc[8] u64.
__device__ __forceinline__ void gemm_core(const float* __restrict__ sXW,
                                          const float* __restrict__ Wg,
                                          const float* __restrict__ bias,
                                          float* __restrict__ sWT,
                                          u64 acc[8], int tid) {
  const int warp = tid >> 5, tx = tid & 31;
  const int rg = warp >> 2, cgq = warp & 3;        // 32 warps worth? no:
  // 24 warps: decompose warp = cg*8 + rg  (cg 0..2, rg 0..7)
  const int cg = warp / 8, rg2 = warp - cg * 8;
  (void)rg; (void)cgq;
  const int c0 = 2 * tx + 64 * cg;
  {
    float2 b = *(const float2*)(bias + c0);
    u64 bp = pack2f(b.x, b.y);
#pragma unroll
    for (int r = 0; r < 8; r++) acc[r] = bp;
  }
  float4 pf[2];
#pragma unroll
  for (int i = 0; i < 2; i++) {
    int t = tid + NT * i, kr = t / 48, cq = t - kr * 48;
    pf[i] = *(const float4*)(Wg + kr * Cc + cq * 4);
  }
  const float* arow = sXW + rg2 * 8 * STR;
  for (int ko = 0; ko < Cc; ko += 32) {
    __syncthreads();  // prior consumers of sWT done
#pragma unroll
    for (int i = 0; i < 2; i++) {
      int t = tid + NT * i, kr = t / 48, cq = t - kr * 48;
      *(float4*)(sWT + kr * Cc + cq * 4) = pf[i];
    }
    __syncthreads();
    if (ko + 32 < Cc) {  // prefetch next W tile under compute
#pragma unroll
      for (int i = 0; i < 2; i++) {
        int t = tid + NT * i, kr = t / 48, cq = t - kr * 48;
        pf[i] = *(const float4*)(Wg + (ko + 32 + kr) * Cc + cq * 4);
      }
    }
#pragma unroll
    for (int kq = 0; kq < 8; kq++) {
      float4 a4[8];
#pragma unroll
      for (int r = 0; r < 8; r++)
        a4[r] = *(const float4*)(arow + r * STR + ko + kq * 4);
#pragma unroll
      for (int kk = 0; kk < 4; kk++) {
        u64 b2 = *(const u64*)(sWT + (kq * 4 + kk) * Cc + c0);
#pragma unroll
        for (int r = 0; r < 8; r++) {
          float av = (kk == 0) ? a4[r].x : (kk == 1) ? a4[r].y
                    : (kk == 2) ? a4[r].z : a4[r].w;
          fma2(acc[r], dup2f(av), b2);
        }
      }
    }
  }
}

__device__ __forceinline__ void gemm_to_smem(const float* __restrict__ sXW,
                                             const float* __restrict__ Wg,
                                             const float* __restrict__ bias,
                                             float* __restrict__ sWT,
                                             float* __restrict__ dst, int tid) {
  u64 acc[8];
  gemm_core(sXW, Wg, bias, sWT, acc, tid);
  const int warp = tid >> 5, tx = tid & 31;
  const int cg = warp / 8, rg = warp - cg * 8;
  const int c0 = 2 * tx + 64 * cg;
#pragma unroll
  for (int r = 0; r < 8; r++)
    *(float2*)(dst + (rg * 8 + r) * STR + c0) = unpack2(acc[r]);
  // ordering: consumer's first __syncthreads covers these stores
}

__device__ __forceinline__ void gemm_skip_out(const float* __restrict__ sXW,
                                              const float* __restrict__ Wg,
                                              const float* __restrict__ bias,
                                              float* __restrict__ sWT,
                                              const float* __restrict__ sAttn,
                                              float* __restrict__ out,
                                              int b, int h0, int w0, int tid) {
  u64 acc[8];
  gemm_core(sXW, Wg, bias, sWT, acc, tid);
  const int warp = tid >> 5, tx = tid & 31;
  const int cg = warp / 8, rg = warp - cg * 8;
  const int c0 = 2 * tx + 64 * cg;
  float lo[8], hi[8];
#pragma unroll
  for (int r = 0; r < 8; r++) {
    float2 v = unpack2(acc[r]);
    lo[r] = v.x + sAttn[(rg * 8 + r) * STR + c0];
    hi[r] = v.y + sAttn[(rg * 8 + r) * STR + c0 + 1];
  }
  // node n = rg*8 + r -> nh = rg, nw = r : contiguous along w.
  float* d0 = out + ((b * Cc + c0) * Hc + h0 + rg) * Wc + w0;
  *(float4*)d0 = make_float4(lo[0], lo[1], lo[2], lo[3]);
  *(float4*)(d0 + 4) = make_float4(lo[4], lo[5], lo[6], lo[7]);
  float* d1 = out + ((b * Cc + c0 + 1) * Hc + h0 + rg) * Wc + w0;
  *(float4*)d1 = make_float4(hi[0], hi[1], hi[2], hi[3]);
  *(float4*)(d1 + 4) = make_float4(hi[4], hi[5], hi[6], hi[7]);
}

__global__ void __launch_bounds__(NT, 1)
wg_kernel(const float* __restrict__ x,
          const float* __restrict__ Wq, const float* __restrict__ bq,
          const float* __restrict__ Wk, const float* __restrict__ bk,
          const float* __restrict__ Wvw, const float* __restrict__ bv,
          const float* __restrict__ Wsk, const float* __restrict__ bsk,
          float* __restrict__ out) {
  extern __shared__ float sm[];
  float* sXW = sm;
  float* sQ = sXW + XW_FLOATS;
  float* sK = sQ + XW_FLOATS;
  float* sV = sK + XW_FLOATS;
  float* sWT = sV + XW_FLOATS;   // 6144 floats; first 4096 alias Gram
  float* sG = sWT;
  float* sSq = sWT + WT_FLOATS;  // 64 floats
  int* sIdx = (int*)(sSq + NN);  // 64*9 ints

  const int tid = threadIdx.x;
  const int w = blockIdx.x;
  const int b = w / (NWH * NWW);
  const int rem = w - b * (NWH * NWW);
  const int wh = rem / NWW, ww = rem - wh * NWW;
  const int h0 = wh * WS, w0 = ww * WS;

  // ---- Phase A: gather window nodes ----
#pragma unroll
  for (int i = 0; i < 2; i++) {
    int t = tid + NT * i;          // 0..1535 : (c, nh)
    int c = t >> 3, nh = t & 7;
    const float* src = x + ((b * Cc + c) * Hc + h0 + nh) * Wc + w0;
    float4 v0 = *(const float4*)src;
    float4 v1 = *(const float4*)(src + 4);
    float* d = sXW + (nh * 8) * STR + c;
    d[0 * STR] = v0.x; d[1 * STR] = v0.y; d[2 * STR] = v0.z; d[3 * STR] = v0.w;
    d[4 * STR] = v1.x; d[5 * STR] = v1.y; d[6 * STR] = v1.z; d[7 * STR] = v1.w;
  }
  __syncthreads();

  // ---- Phase B1: Gram matrix, 512 of 768 threads, 1 row x 8 cols each ----
  if (tid < 512) {
    const int tn = tid >> 3;        // 0..63 (row)
    const int tm8 = tid & 7;        // cols tm8 + 8j
    u64 acc2[8];
#pragma unroll
    for (int j = 0; j < 8; j++) acc2[j] = 0ull;
    const float* ar = sXW + tn * STR;
#pragma unroll 2
    for (int k = 0; k < Cc; k += 4) {
      float4 a = *(const float4*)(ar + k);
      u64 alo = pack2f(a.x, a.y), ahi = pack2f(a.z, a.w);
#pragma unroll
      for (int j = 0; j < 8; j++) {
        float4 bb = *(const float4*)(sXW + (tm8 + 8 * j) * STR + k);
        fma2(acc2[j], alo, pack2f(bb.x, bb.y));
        fma2(acc2[j], ahi, pack2f(bb.z, bb.w));
      }
    }
#pragma unroll
    for (int j = 0; j < 8; j++)
      sG[tn * NN + tm8 + 8 * j] = hsum2(acc2[j]);
  }
  __syncthreads();
  if (tid < NN) sSq[tid] = sG[tid * (NN + 1)];
  __syncthreads();

  // ---- Phase B2: top-9 nearest neighbors (stable, exact fp32) ----
  if (tid < NN) {
    const int n = tid;
    unsigned long long mask = 1ull << n;  // exclude self
    const float sqn = sSq[n];
    const float* grow = sG + n * NN;
#pragma unroll 1
    for (int kk = 0; kk < KK; kk++) {
      float best = 3.0e38f;
      int bi = 0;
#pragma unroll 4
      for (int m = 0; m < NN; m++) {
        float d = sqn + sSq[m] - 2.0f * grow[m];
        if ((mask >> m) & 1ull) d = 3.9e38f;
        if (d < best) { best = d; bi = m; }  // '<' = lowest index wins ties
      }
      mask |= 1ull << bi;
      sIdx[n * KK + kk] = bi;
    }
  }
  __syncthreads();

  // ---- Phase C: Q, K, V projections ----
  gemm_to_smem(sXW, Wq, bq, sWT, sQ, tid);
  gemm_to_smem(sXW, Wk, bk, sWT, sK, tid);
  gemm_to_smem(sXW, Wvw, bv, sWT, sV, tid);
  __syncthreads();  // sQ/sK/sV visible before attention

  // ---- Phase D: 9-neighbor softmax attention; first 512 thr, one (n,h) ----
  if (tid < NN * HEADS) {
    const int n = tid & (NN - 1);
    const int h = tid >> 6;
    const float* qp = sQ + n * STR + h * DH;
    float q[DH];
#pragma unroll
    for (int d4 = 0; d4 < DH / 4; d4++) {
      float4 v = *(const float4*)(qp + d4 * 4);
      q[d4 * 4 + 0] = v.x; q[d4 * 4 + 1] = v.y;
      q[d4 * 4 + 2] = v.z; q[d4 * 4 + 3] = v.w;
    }
    float sc[KK];
    int nb[KK];
#pragma unroll
    for (int kk = 0; kk < KK; kk++) {
      int m = sIdx[n * KK + kk];
      nb[kk] = m;
      const float* kp = sK + m * STR + h * DH;
      float s = 0.0f;
#pragma unroll
      for (int d4 = 0; d4 < DH / 4; d4++) {
        float4 v = *(const float4*)(kp + d4 * 4);
        s = fmaf(q[d4 * 4 + 0], v.x, s);
        s = fmaf(q[d4 * 4 + 1], v.y, s);
        s = fmaf(q[d4 * 4 + 2], v.z, s);
        s = fmaf(q[d4 * 4 + 3], v.w, s);
      }
      sc[kk] = s * INV_SQRT_DH;
    }
    float mx = sc[0];
#pragma unroll
    for (int kk = 1; kk < KK; kk++) mx = fmaxf(mx, sc[kk]);
    float ssum = 0.0f;
#pragma unroll
    for (int kk = 0; kk < KK; kk++) { sc[kk] = __expf(sc[kk] - mx); ssum += sc[kk]; }
    const float inv = 1.0f / ssum;
    float o[DH] = {};
#pragma unroll
    for (int kk = 0; kk < KK; kk++) {
      float a = sc[kk] * inv;
      const float* vp = sV + nb[kk] * STR + h * DH;
#pragma unroll
      for (int d4 = 0; d4 < DH / 4; d4++) {
        float4 v = *(const float4*)(vp + d4 * 4);
        o[d4 * 4 + 0] = fmaf(a, v.x, o[d4 * 4 + 0]);
        o[d4 * 4 + 1] = fmaf(a, v.y, o[d4 * 4 + 1]);
        o[d4 * 4 + 2] = fmaf(a, v.z, o[d4 * 4 + 2]);
        o[d4 * 4 + 3] = fmaf(a, v.w, o[d4 * 4 + 3]);
      }
    }
    float* op = sQ + n * STR + h * DH;  // attn out overwrites own q segment
#pragma unroll
    for (int d4 = 0; d4 < DH / 4; d4++)
      *(float4*)(op + d4 * 4) =
          make_float4(o[d4 * 4 + 0], o[d4 * 4 + 1], o[d4 * 4 + 2], o[d4 * 4 + 3]);
  }
  // first __syncthreads inside gemm_skip_out guards sQ (attn) reads

  // ---- Phase E: skip GEMM + attn add + scatter to [B,C,H,W] ----
  gemm_skip_out(sXW, Wsk, bsk, sWT, sQ, out, b, h0, w0, tid);
}

extern "C" void kernel_launch(void* const* d_in, const int* in_sizes, int n_in,
                              void* d_out, int out_size) {
  const float* x   = (const float*)d_in[0];
  const float* Wq  = (const float*)d_in[1];
  const float* bq  = (const float*)d_in[2];
  const float* Wk  = (const float*)d_in[3];
  const float* bk  = (const float*)d_in[4];
  const float* Wv  = (const float*)d_in[5];
  const float* bv  = (const float*)d_in[6];
  const float* Wsk = (const float*)d_in[7];
  const float* bsk = (const float*)d_in[8];
  float* out = (float*)d_out;

  cudaFuncSetAttribute(wg_kernel, cudaFuncAttributeMaxDynamicSharedMemorySize,
                       (int)SMEM_BYTES);
  wg_kernel<<<WB, NT, SMEM_BYTES>>>(x, Wq, bq, Wk, bk, Wv, bv, Wsk, bsk, out);
}

// round 7
// speedup vs baseline: 1.1113x; 1.1028x over previous
#include <cuda_runtime.h>

// ---------------------------------------------------------------------------
// WindowGrapherPyg fused kernel, R6: tensor-core GEMMs (mma.sync tf32 x3
// error-compensated = fp32 accuracy), scalar exact Gram/KNN, fused attention.
// One CTA (512 thr, 16 warps) per 8x8 window.
// Warp grid for GEMM: mt = warp>>2 (16-row M tile), wg = warp&3 (48-col group).
// m16n8k8 fragment map (lane = 4*g+tig ... g=lane>>2, tig=lane&3):
//   A: a0=(g,tig) a1=(g+8,tig) a2=(g,tig+4) a3=(g+8,tig+4)   [row-major]
//   B: b0=(k=tig,n=g) b1=(k=tig+4,n=g)                       [col fragment]
//   D: c0=(g,2tig) c1=(g,2tig+1) c2=(g+8,2tig) c3=(g+8,2tig+1)
// ---------------------------------------------------------------------------

typedef unsigned long long u64;

namespace {
constexpr int Bc = 2, Cc = 192, Hc = 192, Wc = 192;
constexpr int WS = 8, NN = 64, KK = 9, HEADS = 8, DH = 24;
constexpr int NWH = Hc / WS, NWW = Wc / WS;         // 24 x 24
constexpr int WB = Bc * NWH * NWW;                  // 1152 windows
constexpr int STR = 196;                            // xw/Q/K/V row stride
constexpr int WSTR = 200;                           // staged W tile row stride
constexpr int NT = 512;
constexpr int XW_FLOATS = NN * STR;                 // 12544
constexpr int WT_FLOATS = 32 * WSTR;                // 6400 (aliases Gram 4096)
constexpr size_t SMEM_BYTES =
    (size_t)(4 * XW_FLOATS + WT_FLOATS + NN) * sizeof(float) +
    (size_t)(NN * KK) * sizeof(int);                // 228,864 B
constexpr float INV_SQRT_DH = 0.20412414523193154f;
}

__device__ __forceinline__ u64 pack2f(float x, float y) {
  u64 r; asm("mov.b64 %0, {%1, %2};" : "=l"(r) : "f"(x), "f"(y)); return r;
}
__device__ __forceinline__ void fma2(u64& d, u64 a, u64 b) {
  asm("fma.rn.f32x2 %0, %1, %2, %0;" : "+l"(d) : "l"(a), "l"(b));
}
__device__ __forceinline__ float hsum2(u64 v) {
  float2 o; asm("mov.b64 {%0, %1}, %2;" : "=f"(o.x), "=f"(o.y) : "l"(v));
  return o.x + o.y;
}
__device__ __forceinline__ unsigned cvt_tf32(float f) {
  unsigned r; asm("cvt.rna.tf32.f32 %0, %1;" : "=r"(r) : "f"(f)); return r;
}
__device__ __forceinline__ void split_tf32(float f, unsigned& hi, unsigned& lo) {
  hi = cvt_tf32(f);
  lo = cvt_tf32(f - __uint_as_float(hi));
}
__device__ __forceinline__ void mma_tf32(float d[4], unsigned a0, unsigned a1,
                                         unsigned a2, unsigned a3,
                                         unsigned b0, unsigned b1) {
  asm("mma.sync.aligned.m16n8k8.row.col.f32.tf32.tf32.f32 "
      "{%0,%1,%2,%3}, {%4,%5,%6,%7}, {%8,%9}, {%0,%1,%2,%3};"
      : "+f"(d[0]), "+f"(d[1]), "+f"(d[2]), "+f"(d[3])
      : "r"(a0), "r"(a1), "r"(a2), "r"(a3), "r"(b0), "r"(b1));
}

// acc[6][4]: 6 n-tiles (8 cols each) for this warp's 16x48 output tile.
__device__ __forceinline__ void gemm_core(const float* __restrict__ sXW,
                                          const float* __restrict__ Wg,
                                          float* __restrict__ sWT,
                                          float acc[6][4], int tid) {
  const int warp = tid >> 5, lane = tid & 31;
  const int g = lane >> 2, tig = lane & 3;
  const int mt = warp >> 2, wg = warp & 3;
  const int r0 = mt * 16 + g;
  const int n0 = wg * 48;
#pragma unroll
  for (int j = 0; j < 6; j++)
#pragma unroll
    for (int q = 0; q < 4; q++) acc[j][q] = 0.0f;

  float4 pf[3];
#pragma unroll
  for (int i = 0; i < 3; i++) {
    int t = tid + NT * i, kr = t / 48, cq = t - kr * 48;
    pf[i] = *(const float4*)(Wg + kr * Cc + cq * 4);
  }
  for (int ko = 0; ko < Cc; ko += 32) {
    __syncthreads();  // prior consumers of sWT done
#pragma unroll
    for (int i = 0; i < 3; i++) {
      int t = tid + NT * i, kr = t / 48, cq = t - kr * 48;
      *(float4*)(sWT + kr * WSTR + cq * 4) = pf[i];
    }
    __syncthreads();
    if (ko + 32 < Cc) {  // prefetch next W tile under compute
#pragma unroll
      for (int i = 0; i < 3; i++) {
        int t = tid + NT * i, kr = t / 48, cq = t - kr * 48;
        pf[i] = *(const float4*)(Wg + (ko + 32 + kr) * Cc + cq * 4);
      }
    }
#pragma unroll
    for (int ks = 0; ks < 4; ks++) {
      const float* ap = sXW + r0 * STR + ko + ks * 8 + tig;
      unsigned ah[4], al[4];
      split_tf32(ap[0],           ah[0], al[0]);
      split_tf32(ap[8 * STR],     ah[1], al[1]);
      split_tf32(ap[4],           ah[2], al[2]);
      split_tf32(ap[8 * STR + 4], ah[3], al[3]);
      const float* bp = sWT + (ks * 8 + tig) * WSTR + n0 + g;
#pragma unroll
      for (int j = 0; j < 6; j++) {
        unsigned bh0, bl0, bh1, bl1;
        split_tf32(bp[8 * j], bh0, bl0);
        split_tf32(bp[4 * WSTR + 8 * j], bh1, bl1);
        mma_tf32(acc[j], ah[0], ah[1], ah[2], ah[3], bh0, bh1);
        mma_tf32(acc[j], ah[0], ah[1], ah[2], ah[3], bl0, bl1);
        mma_tf32(acc[j], al[0], al[1], al[2], al[3], bh0, bh1);
      }
    }
  }
}

__device__ __forceinline__ void gemm_to_smem(const float* __restrict__ sXW,
                                             const float* __restrict__ Wg,
                                             const float* __restrict__ bias,
                                             float* __restrict__ sWT,
                                             float* __restrict__ dst, int tid) {
  float acc[6][4];
  gemm_core(sXW, Wg, sWT, acc, tid);
  const int warp = tid >> 5, lane = tid & 31;
  const int g = lane >> 2, tig = lane & 3;
  const int mt = warp >> 2, wg = warp & 3;
  const int r0 = mt * 16 + g;
#pragma unroll
  for (int j = 0; j < 6; j++) {
    const int c = wg * 48 + 8 * j + 2 * tig;
    float2 bj = *(const float2*)(bias + c);
    *(float2*)(dst + r0 * STR + c) =
        make_float2(acc[j][0] + bj.x, acc[j][1] + bj.y);
    *(float2*)(dst + (r0 + 8) * STR + c) =
        make_float2(acc[j][2] + bj.x, acc[j][3] + bj.y);
  }
  // ordering: next consumer's first __syncthreads covers these stores
}

__device__ __forceinline__ void gemm_skip_out(const float* __restrict__ sXW,
                                              const float* __restrict__ Wg,
                                              const float* __restrict__ bias,
                                              float* __restrict__ sWT,
                                              const float* __restrict__ sAttn,
                                              float* __restrict__ out,
                                              int b, int h0, int w0, int tid) {
  float acc[6][4];
  gemm_core(sXW, Wg, sWT, acc, tid);
  const int warp = tid >> 5, lane = tid & 31;
  const int g = lane >> 2, tig = lane & 3;
  const int mt = warp >> 2, wg = warp & 3;
  const int r0 = mt * 16 + g;       // node row 1 (nh=2mt,   nw=g)
  const int r1 = r0 + 8;            // node row 2 (nh=2mt+1, nw=g)
  const long hw0 = (long)(h0 + 2 * mt) * Wc + w0 + g;
  const long hw1 = hw0 + Wc;        // next nh row
#pragma unroll
  for (int j = 0; j < 6; j++) {
    const int c = wg * 48 + 8 * j + 2 * tig;
    float2 bj = *(const float2*)(bias + c);
    float v00 = acc[j][0] + bj.x + sAttn[r0 * STR + c];
    float v01 = acc[j][1] + bj.y + sAttn[r0 * STR + c + 1];
    float v10 = acc[j][2] + bj.x + sAttn[r1 * STR + c];
    float v11 = acc[j][3] + bj.y + sAttn[r1 * STR + c + 1];
    float* base0 = out + (long)(b * Cc + c) * Hc * Wc;
    float* base1 = out + (long)(b * Cc + c + 1) * Hc * Wc;
    base0[hw0] = v00; base1[hw0] = v01;
    base0[hw1] = v10; base1[hw1] = v11;
  }
}

__global__ void __launch_bounds__(NT, 1)
wg_kernel(const float* __restrict__ x,
          const float* __restrict__ Wq, const float* __restrict__ bq,
          const float* __restrict__ Wk, const float* __restrict__ bk,
          const float* __restrict__ Wvw, const float* __restrict__ bv,
          const float* __restrict__ Wsk, const float* __restrict__ bsk,
          float* __restrict__ out) {
  extern __shared__ float sm[];
  float* sXW = sm;
  float* sQ = sXW + XW_FLOATS;
  float* sK = sQ + XW_FLOATS;
  float* sV = sK + XW_FLOATS;
  float* sWT = sV + XW_FLOATS;   // 6400 floats; first 4096 alias Gram
  float* sG = sWT;
  float* sSq = sWT + WT_FLOATS;  // 64 floats
  int* sIdx = (int*)(sSq + NN);  // 64*9 ints

  const int tid = threadIdx.x;
  const int w = blockIdx.x;
  const int b = w / (NWH * NWW);
  const int rem = w - b * (NWH * NWW);
  const int wh = rem / NWW, ww = rem - wh * NWW;
  const int h0 = wh * WS, w0 = ww * WS;

  // ---- Phase A: gather window nodes ----
#pragma unroll
  for (int i = 0; i < 3; i++) {
    int t = tid + NT * i;          // 0..1535 : (c, nh)
    int c = t >> 3, nh = t & 7;
    const float* src = x + ((b * Cc + c) * Hc + h0 + nh) * Wc + w0;
    float4 v0 = *(const float4*)src;
    float4 v1 = *(const float4*)(src + 4);
    float* d = sXW + (nh * 8) * STR + c;
    d[0 * STR] = v0.x; d[1 * STR] = v0.y; d[2 * STR] = v0.z; d[3 * STR] = v0.w;
    d[4 * STR] = v1.x; d[5 * STR] = v1.y; d[6 * STR] = v1.z; d[7 * STR] = v1.w;
  }
  __syncthreads();

  // ---- Phase B1: Gram matrix, 512 threads, 1 row x 8 cols per thread ----
  {
    const int tn = tid >> 3;        // 0..63 (row)
    const int tm8 = tid & 7;        // cols tm8 + 8j
    u64 acc2[8];
#pragma unroll
    for (int j = 0; j < 8; j++) acc2[j] = 0ull;
    const float* ar = sXW + tn * STR;
#pragma unroll 2
    for (int k = 0; k < Cc; k += 4) {
      float4 a = *(const float4*)(ar + k);
      u64 alo = pack2f(a.x, a.y), ahi = pack2f(a.z, a.w);
#pragma unroll
      for (int j = 0; j < 8; j++) {
        float4 bb = *(const float4*)(sXW + (tm8 + 8 * j) * STR + k);
        fma2(acc2[j], alo, pack2f(bb.x, bb.y));
        fma2(acc2[j], ahi, pack2f(bb.z, bb.w));
      }
    }
#pragma unroll
    for (int j = 0; j < 8; j++)
      sG[tn * NN + tm8 + 8 * j] = hsum2(acc2[j]);
  }
  __syncthreads();
  if (tid < NN) sSq[tid] = sG[tid * (NN + 1)];
  __syncthreads();

  // ---- Phase B2: top-9 nearest neighbors (stable, exact fp32) ----
  if (tid < NN) {
    const int n = tid;
    unsigned long long mask = 1ull << n;  // exclude self
    const float sqn = sSq[n];
    const float* grow = sG + n * NN;
#pragma unroll 1
    for (int kk = 0; kk < KK; kk++) {
      float best = 3.0e38f;
      int bi = 0;
#pragma unroll 4
      for (int m = 0; m < NN; m++) {
        float d = sqn + sSq[m] - 2.0f * grow[m];
        if ((mask >> m) & 1ull) d = 3.9e38f;
        if (d < best) { best = d; bi = m; }  // '<' = lowest index wins ties
      }
      mask |= 1ull << bi;
      sIdx[n * KK + kk] = bi;
    }
  }
  __syncthreads();

  // ---- Phase C: Q, K, V projections (tensor core, 3xTF32) ----
  gemm_to_smem(sXW, Wq, bq, sWT, sQ, tid);
  gemm_to_smem(sXW, Wk, bk, sWT, sK, tid);
  gemm_to_smem(sXW, Wvw, bv, sWT, sV, tid);
  __syncthreads();  // sQ/sK/sV visible before attention

  // ---- Phase D: 9-neighbor softmax attention; 512 thr = one (n,h) each ----
  {
    const int n = tid & (NN - 1);
    const int h = tid >> 6;
    const float* qp = sQ + n * STR + h * DH;
    float q[DH];
#pragma unroll
    for (int d4 = 0; d4 < DH / 4; d4++) {
      float4 v = *(const float4*)(qp + d4 * 4);
      q[d4 * 4 + 0] = v.x; q[d4 * 4 + 1] = v.y;
      q[d4 * 4 + 2] = v.z; q[d4 * 4 + 3] = v.w;
    }
    float sc[KK];
    int nb[KK];
#pragma unroll
    for (int kk = 0; kk < KK; kk++) {
      int m = sIdx[n * KK + kk];
      nb[kk] = m;
      const float* kp = sK + m * STR + h * DH;
      float s = 0.0f;
#pragma unroll
      for (int d4 = 0; d4 < DH / 4; d4++) {
        float4 v = *(const float4*)(kp + d4 * 4);
        s = fmaf(q[d4 * 4 + 0], v.x, s);
        s = fmaf(q[d4 * 4 + 1], v.y, s);
        s = fmaf(q[d4 * 4 + 2], v.z, s);
        s = fmaf(q[d4 * 4 + 3], v.w, s);
      }
      sc[kk] = s * INV_SQRT_DH;
    }
    float mx = sc[0];
#pragma unroll
    for (int kk = 1; kk < KK; kk++) mx = fmaxf(mx, sc[kk]);
    float ssum = 0.0f;
#pragma unroll
    for (int kk = 0; kk < KK; kk++) { sc[kk] = __expf(sc[kk] - mx); ssum += sc[kk]; }
    const float inv = 1.0f / ssum;
    float o[DH] = {};
#pragma unroll
    for (int kk = 0; kk < KK; kk++) {
      float a = sc[kk] * inv;
      const float* vp = sV + nb[kk] * STR + h * DH;
#pragma unroll
      for (int d4 = 0; d4 < DH / 4; d4++) {
        float4 v = *(const float4*)(vp + d4 * 4);
        o[d4 * 4 + 0] = fmaf(a, v.x, o[d4 * 4 + 0]);
        o[d4 * 4 + 1] = fmaf(a, v.y, o[d4 * 4 + 1]);
        o[d4 * 4 + 2] = fmaf(a, v.z, o[d4 * 4 + 2]);
        o[d4 * 4 + 3] = fmaf(a, v.w, o[d4 * 4 + 3]);
      }
    }
    float* op = sQ + n * STR + h * DH;  // attn out overwrites own q segment
#pragma unroll
    for (int d4 = 0; d4 < DH / 4; d4++)
      *(float4*)(op + d4 * 4) =
          make_float4(o[d4 * 4 + 0], o[d4 * 4 + 1], o[d4 * 4 + 2], o[d4 * 4 + 3]);
  }
  // first __syncthreads inside gemm_skip_out guards sQ (attn) reads

  // ---- Phase E: skip GEMM + attn add + scatter to [B,C,H,W] ----
  gemm_skip_out(sXW, Wsk, bsk, sWT, sQ, out, b, h0, w0, tid);
}

extern "C" void kernel_launch(void* const* d_in, const int* in_sizes, int n_in,
                              void* d_out, int out_size) {
  const float* x   = (const float*)d_in[0];
  const float* Wq  = (const float*)d_in[1];
  const float* bq  = (const float*)d_in[2];
  const float* Wk  = (const float*)d_in[3];
  const float* bk  = (const float*)d_in[4];
  const float* Wv  = (const float*)d_in[5];
  const float* bv  = (const float*)d_in[6];
  const float* Wsk = (const float*)d_in[7];
  const float* bsk = (const float*)d_in[8];
  float* out = (float*)d_out;

  cudaFuncSetAttribute(wg_kernel, cudaFuncAttributeMaxDynamicSharedMemorySize,
                       (int)SMEM_BYTES);
  wg_kernel<<<WB, NT, SMEM_BYTES>>>(x, Wq, bq, Wk, bk, Wv, bv, Wsk, bsk, out);
}

// round 8
// speedup vs baseline: 1.1401x; 1.0259x over previous
#include <cuda_runtime.h>

// ---------------------------------------------------------------------------
// WindowGrapherPyg fused kernel, R7: tensor-core GEMMs (mma.sync tf32 x3),
// W hi/lo split PRECOMPUTED into __device__ globals by a prologue kernel
// (removes all B-operand cvt.tf32 from the hot loop; R6's 31% ALU wall).
// One CTA (512 thr, 16 warps) per 8x8 window.
// m16n8k8 fragment map (lane = 4*g+tig):
//   A: a0=(g,tig) a1=(g+8,tig) a2=(g,tig+4) a3=(g+8,tig+4)   [row-major]
//   B: b0=(k=tig,n=g) b1=(k=tig+4,n=g)
//   D: c0=(g,2tig) c1=(g,2tig+1) c2=(g+8,2tig) c3=(g+8,2tig+1)
// ---------------------------------------------------------------------------

typedef unsigned long long u64;

namespace {
constexpr int Bc = 2, Cc = 192, Hc = 192, Wc = 192;
constexpr int WS = 8, NN = 64, KK = 9, HEADS = 8, DH = 24;
constexpr int NWH = Hc / WS, NWW = Wc / WS;         // 24 x 24
constexpr int WB = Bc * NWH * NWW;                  // 1152 windows
constexpr int STR = 196;                            // xw/Q/K/V row stride
constexpr int WSTR = 200;                           // staged W tile row stride
constexpr int NT = 512;
constexpr int XW_FLOATS = NN * STR;                 // 12544
constexpr int WT_FLOATS = 2 * 16 * WSTR;            // 6400 (hi+lo tiles)
constexpr int WELEMS = Cc * Cc;                     // 36864 per matrix
constexpr size_t SMEM_BYTES =
    (size_t)(4 * XW_FLOATS + WT_FLOATS + NN) * sizeof(float) +
    (size_t)(NN * KK) * sizeof(int);                // 228,864 B
constexpr float INV_SQRT_DH = 0.20412414523193154f;
}

// Precomputed tf32 hi/lo decompositions of the 4 weight matrices.
__device__ float g_Whi[4 * WELEMS];
__device__ float g_Wlo[4 * WELEMS];

__device__ __forceinline__ u64 pack2f(float x, float y) {
  u64 r; asm("mov.b64 %0, {%1, %2};" : "=l"(r) : "f"(x), "f"(y)); return r;
}
__device__ __forceinline__ void fma2(u64& d, u64 a, u64 b) {
  asm("fma.rn.f32x2 %0, %1, %2, %0;" : "+l"(d) : "l"(a), "l"(b));
}
__device__ __forceinline__ float hsum2(u64 v) {
  float2 o; asm("mov.b64 {%0, %1}, %2;" : "=f"(o.x), "=f"(o.y) : "l"(v));
  return o.x + o.y;
}
__device__ __forceinline__ unsigned cvt_tf32(float f) {
  unsigned r; asm("cvt.rna.tf32.f32 %0, %1;" : "=r"(r) : "f"(f)); return r;
}
__device__ __forceinline__ void split_tf32(float f, unsigned& hi, unsigned& lo) {
  hi = cvt_tf32(f);
  lo = cvt_tf32(f - __uint_as_float(hi));
}
__device__ __forceinline__ void mma_tf32(float d[4], unsigned a0, unsigned a1,
                                         unsigned a2, unsigned a3,
                                         unsigned b0, unsigned b1) {
  asm("mma.sync.aligned.m16n8k8.row.col.f32.tf32.tf32.f32 "
      "{%0,%1,%2,%3}, {%4,%5,%6,%7}, {%8,%9}, {%0,%1,%2,%3};"
      : "+f"(d[0]), "+f"(d[1]), "+f"(d[2]), "+f"(d[3])
      : "r"(a0), "r"(a1), "r"(a2), "r"(a3), "r"(b0), "r"(b1));
}

// Prologue: split all 4 weight matrices into tf32 hi/lo (both stored as the
// fp32 bit-patterns of valid tf32 values -> zero cvt in the GEMM hot loop).
__global__ void split_w_kernel(const float* __restrict__ w0,
                               const float* __restrict__ w1,
                               const float* __restrict__ w2,
                               const float* __restrict__ w3) {
  int i = blockIdx.x * blockDim.x + threadIdx.x;
  if (i >= 4 * WELEMS) return;
  int m = i / WELEMS, r = i - m * WELEMS;
  const float* src = (m == 0) ? w0 : (m == 1) ? w1 : (m == 2) ? w2 : w3;
  float f = src[r];
  unsigned hi, lo;
  split_tf32(f, hi, lo);
  g_Whi[i] = __uint_as_float(hi);
  g_Wlo[i] = __uint_as_float(lo);
}

// acc[6][4]: warp's 16x48 output tile (6 n-tiles of 8 cols).
__device__ __forceinline__ void gemm_core(const float* __restrict__ sXW,
                                          const float* __restrict__ whi,
                                          const float* __restrict__ wlo,
                                          float* __restrict__ sWT,
                                          float acc[6][4], int tid) {
  float* sWHi = sWT;
  float* sWLo = sWT + 16 * WSTR;
  const int warp = tid >> 5, lane = tid & 31;
  const int g = lane >> 2, tig = lane & 3;
  const int mt = warp >> 2, wg = warp & 3;
  const int r0 = mt * 16 + g;
  const int n0 = wg * 48;
#pragma unroll
  for (int j = 0; j < 6; j++)
#pragma unroll
    for (int q = 0; q < 4; q++) acc[j][q] = 0.0f;

  // Stage decomposition: 1536 float4 per 16-row hi+lo pair; 3 per thread.
  float4 pf[3];
#pragma unroll
  for (int i = 0; i < 3; i++) {
    int t = tid + NT * i;
    bool ishi = t < 768;
    int u = ishi ? t : t - 768;
    int kr = u / 48, cq = u - kr * 48;
    pf[i] = *(const float4*)((ishi ? whi : wlo) + kr * Cc + cq * 4);
  }
  for (int ko = 0; ko < Cc; ko += 16) {
    __syncthreads();  // prior consumers of sWT done
#pragma unroll
    for (int i = 0; i < 3; i++) {
      int t = tid + NT * i;
      bool ishi = t < 768;
      int u = ishi ? t : t - 768;
      int kr = u / 48, cq = u - kr * 48;
      *(float4*)((ishi ? sWHi : sWLo) + kr * WSTR + cq * 4) = pf[i];
    }
    __syncthreads();
    if (ko + 16 < Cc) {  // prefetch next tile pair under compute
#pragma unroll
      for (int i = 0; i < 3; i++) {
        int t = tid + NT * i;
        bool ishi = t < 768;
        int u = ishi ? t : t - 768;
        int kr = u / 48, cq = u - kr * 48;
        pf[i] = *(const float4*)((ishi ? whi : wlo) + (ko + 16 + kr) * Cc + cq * 4);
      }
    }
#pragma unroll
    for (int ks = 0; ks < 2; ks++) {
      const float* ap = sXW + r0 * STR + ko + ks * 8 + tig;
      unsigned ah[4], al[4];
      split_tf32(ap[0],           ah[0], al[0]);
      split_tf32(ap[8 * STR],     ah[1], al[1]);
      split_tf32(ap[4],           ah[2], al[2]);
      split_tf32(ap[8 * STR + 4], ah[3], al[3]);
      const float* bhp = sWHi + (ks * 8 + tig) * WSTR + n0 + g;
      const float* blp = sWLo + (ks * 8 + tig) * WSTR + n0 + g;
#pragma unroll
      for (int j = 0; j < 6; j++) {
        unsigned bh0 = __float_as_uint(bhp[8 * j]);
        unsigned bh1 = __float_as_uint(bhp[4 * WSTR + 8 * j]);
        unsigned bl0 = __float_as_uint(blp[8 * j]);
        unsigned bl1 = __float_as_uint(blp[4 * WSTR + 8 * j]);
        mma_tf32(acc[j], ah[0], ah[1], ah[2], ah[3], bh0, bh1);
        mma_tf32(acc[j], ah[0], ah[1], ah[2], ah[3], bl0, bl1);
        mma_tf32(acc[j], al[0], al[1], al[2], al[3], bh0, bh1);
      }
    }
  }
}

__device__ __forceinline__ void gemm_to_smem(const float* __restrict__ sXW,
                                             const float* __restrict__ whi,
                                             const float* __restrict__ wlo,
                                             const float* __restrict__ bias,
                                             float* __restrict__ sWT,
                                             float* __restrict__ dst, int tid) {
  float acc[6][4];
  gemm_core(sXW, whi, wlo, sWT, acc, tid);
  const int warp = tid >> 5, lane = tid & 31;
  const int g = lane >> 2, tig = lane & 3;
  const int mt = warp >> 2, wg = warp & 3;
  const int r0 = mt * 16 + g;
#pragma unroll
  for (int j = 0; j < 6; j++) {
    const int c = wg * 48 + 8 * j + 2 * tig;
    float2 bj = *(const float2*)(bias + c);
    *(float2*)(dst + r0 * STR + c) =
        make_float2(acc[j][0] + bj.x, acc[j][1] + bj.y);
    *(float2*)(dst + (r0 + 8) * STR + c) =
        make_float2(acc[j][2] + bj.x, acc[j][3] + bj.y);
  }
  // ordering: next consumer's first __syncthreads covers these stores
}

__device__ __forceinline__ void gemm_skip_out(const float* __restrict__ sXW,
                                              const float* __restrict__ whi,
                                              const float* __restrict__ wlo,
                                              const float* __restrict__ bias,
                                              float* __restrict__ sWT,
                                              const float* __restrict__ sAttn,
                                              float* __restrict__ out,
                                              int b, int h0, int w0, int tid) {
  float acc[6][4];
  gemm_core(sXW, whi, wlo, sWT, acc, tid);
  const int warp = tid >> 5, lane = tid & 31;
  const int g = lane >> 2, tig = lane & 3;
  const int mt = warp >> 2, wg = warp & 3;
  const int r0 = mt * 16 + g;       // node (nh=2mt,   nw=g)
  const int r1 = r0 + 8;            // node (nh=2mt+1, nw=g)
  const long hw0 = (long)(h0 + 2 * mt) * Wc + w0 + g;
  const long hw1 = hw0 + Wc;
#pragma unroll
  for (int j = 0; j < 6; j++) {
    const int c = wg * 48 + 8 * j + 2 * tig;
    float2 bj = *(const float2*)(bias + c);
    float v00 = acc[j][0] + bj.x + sAttn[r0 * STR + c];
    float v01 = acc[j][1] + bj.y + sAttn[r0 * STR + c + 1];
    float v10 = acc[j][2] + bj.x + sAttn[r1 * STR + c];
    float v11 = acc[j][3] + bj.y + sAttn[r1 * STR + c + 1];
    float* base0 = out + (long)(b * Cc + c) * Hc * Wc;
    float* base1 = out + (long)(b * Cc + c + 1) * Hc * Wc;
    base0[hw0] = v00; base1[hw0] = v01;
    base0[hw1] = v10; base1[hw1] = v11;
  }
}

__global__ void __launch_bounds__(NT, 1)
wg_kernel(const float* __restrict__ x,
          const float* __restrict__ bq, const float* __restrict__ bk,
          const float* __restrict__ bv, const float* __restrict__ bsk,
          float* __restrict__ out) {
  extern __shared__ float sm[];
  float* sXW = sm;
  float* sQ = sXW + XW_FLOATS;
  float* sK = sQ + XW_FLOATS;
  float* sV = sK + XW_FLOATS;
  float* sWT = sV + XW_FLOATS;   // 6400 floats; first 4096 alias Gram
  float* sG = sWT;
  float* sSq = sWT + WT_FLOATS;  // 64 floats
  int* sIdx = (int*)(sSq + NN);  // 64*9 ints

  const int tid = threadIdx.x;
  const int w = blockIdx.x;
  const int b = w / (NWH * NWW);
  const int rem = w - b * (NWH * NWW);
  const int wh = rem / NWW, ww = rem - wh * NWW;
  const int h0 = wh * WS, w0 = ww * WS;

  // ---- Phase A: gather window nodes ----
#pragma unroll
  for (int i = 0; i < 3; i++) {
    int t = tid + NT * i;          // 0..1535 : (c, nh)
    int c = t >> 3, nh = t & 7;
    const float* src = x + ((b * Cc + c) * Hc + h0 + nh) * Wc + w0;
    float4 v0 = *(const float4*)src;
    float4 v1 = *(const float4*)(src + 4);
    float* d = sXW + (nh * 8) * STR + c;
    d[0 * STR] = v0.x; d[1 * STR] = v0.y; d[2 * STR] = v0.z; d[3 * STR] = v0.w;
    d[4 * STR] = v1.x; d[5 * STR] = v1.y; d[6 * STR] = v1.z; d[7 * STR] = v1.w;
  }
  __syncthreads();

  // ---- Phase B1: Gram matrix (exact fp32), 1 row x 8 cols per thread ----
  {
    const int tn = tid >> 3;        // 0..63 (row)
    const int tm8 = tid & 7;        // cols tm8 + 8j
    u64 acc2[8];
#pragma unroll
    for (int j = 0; j < 8; j++) acc2[j] = 0ull;
    const float* ar = sXW + tn * STR;
#pragma unroll 2
    for (int k = 0; k < Cc; k += 4) {
      float4 a = *(const float4*)(ar + k);
      u64 alo = pack2f(a.x, a.y), ahi = pack2f(a.z, a.w);
#pragma unroll
      for (int j = 0; j < 8; j++) {
        float4 bb = *(const float4*)(sXW + (tm8 + 8 * j) * STR + k);
        fma2(acc2[j], alo, pack2f(bb.x, bb.y));
        fma2(acc2[j], ahi, pack2f(bb.z, bb.w));
      }
    }
#pragma unroll
    for (int j = 0; j < 8; j++)
      sG[tn * NN + tm8 + 8 * j] = hsum2(acc2[j]);
  }
  __syncthreads();
  if (tid < NN) sSq[tid] = sG[tid * (NN + 1)];
  __syncthreads();

  // ---- Phase B2: top-9 nearest neighbors (stable, exact fp32) ----
  if (tid < NN) {
    const int n = tid;
    unsigned long long mask = 1ull << n;  // exclude self
    const float sqn = sSq[n];
    const float* grow = sG + n * NN;
#pragma unroll 1
    for (int kk = 0; kk < KK; kk++) {
      float best = 3.0e38f;
      int bi = 0;
#pragma unroll 4
      for (int m = 0; m < NN; m++) {
        float d = sqn + sSq[m] - 2.0f * grow[m];
        if ((mask >> m) & 1ull) d = 3.9e38f;
        if (d < best) { best = d; bi = m; }  // '<' = lowest index wins ties
      }
      mask |= 1ull << bi;
      sIdx[n * KK + kk] = bi;
    }
  }
  __syncthreads();

  // ---- Phase C: Q, K, V projections (tensor core, 3xTF32) ----
  gemm_to_smem(sXW, g_Whi + 0 * WELEMS, g_Wlo + 0 * WELEMS, bq, sWT, sQ, tid);
  gemm_to_smem(sXW, g_Whi + 1 * WELEMS, g_Wlo + 1 * WELEMS, bk, sWT, sK, tid);
  gemm_to_smem(sXW, g_Whi + 2 * WELEMS, g_Wlo + 2 * WELEMS, bv, sWT, sV, tid);
  __syncthreads();  // sQ/sK/sV visible before attention

  // ---- Phase D: 9-neighbor softmax attention; 512 thr = one (n,h) each ----
  {
    const int n = tid & (NN - 1);
    const int h = tid >> 6;
    const float* qp = sQ + n * STR + h * DH;
    float q[DH];
#pragma unroll
    for (int d4 = 0; d4 < DH / 4; d4++) {
      float4 v = *(const float4*)(qp + d4 * 4);
      q[d4 * 4 + 0] = v.x; q[d4 * 4 + 1] = v.y;
      q[d4 * 4 + 2] = v.z; q[d4 * 4 + 3] = v.w;
    }
    float sc[KK];
    int nb[KK];
#pragma unroll
    for (int kk = 0; kk < KK; kk++) {
      int m = sIdx[n * KK + kk];
      nb[kk] = m;
      const float* kp = sK + m * STR + h * DH;
      float s = 0.0f;
#pragma unroll
      for (int d4 = 0; d4 < DH / 4; d4++) {
        float4 v = *(const float4*)(kp + d4 * 4);
        s = fmaf(q[d4 * 4 + 0], v.x, s);
        s = fmaf(q[d4 * 4 + 1], v.y, s);
        s = fmaf(q[d4 * 4 + 2], v.z, s);
        s = fmaf(q[d4 * 4 + 3], v.w, s);
      }
      sc[kk] = s * INV_SQRT_DH;
    }
    float mx = sc[0];
#pragma unroll
    for (int kk = 1; kk < KK; kk++) mx = fmaxf(mx, sc[kk]);
    float ssum = 0.0f;
#pragma unroll
    for (int kk = 0; kk < KK; kk++) { sc[kk] = __expf(sc[kk] - mx); ssum += sc[kk]; }
    const float inv = 1.0f / ssum;
    float o[DH] = {};
#pragma unroll
    for (int kk = 0; kk < KK; kk++) {
      float a = sc[kk] * inv;
      const float* vp = sV + nb[kk] * STR + h * DH;
#pragma unroll
      for (int d4 = 0; d4 < DH / 4; d4++) {
        float4 v = *(const float4*)(vp + d4 * 4);
        o[d4 * 4 + 0] = fmaf(a, v.x, o[d4 * 4 + 0]);
        o[d4 * 4 + 1] = fmaf(a, v.y, o[d4 * 4 + 1]);
        o[d4 * 4 + 2] = fmaf(a, v.z, o[d4 * 4 + 2]);
        o[d4 * 4 + 3] = fmaf(a, v.w, o[d4 * 4 + 3]);
      }
    }
    float* op = sQ + n * STR + h * DH;  // attn out overwrites own q segment
#pragma unroll
    for (int d4 = 0; d4 < DH / 4; d4++)
      *(float4*)(op + d4 * 4) =
          make_float4(o[d4 * 4 + 0], o[d4 * 4 + 1], o[d4 * 4 + 2], o[d4 * 4 + 3]);
  }
  // first __syncthreads inside gemm_skip_out guards sQ (attn) reads

  // ---- Phase E: skip GEMM + attn add + scatter to [B,C,H,W] ----
  gemm_skip_out(sXW, g_Whi + 3 * WELEMS, g_Wlo + 3 * WELEMS, bsk, sWT, sQ,
                out, b, h0, w0, tid);
}

extern "C" void kernel_launch(void* const* d_in, const int* in_sizes, int n_in,
                              void* d_out, int out_size) {
  const float* x   = (const float*)d_in[0];
  const float* Wq  = (const float*)d_in[1];
  const float* bq  = (const float*)d_in[2];
  const float* Wk  = (const float*)d_in[3];
  const float* bk  = (const float*)d_in[4];
  const float* Wv  = (const float*)d_in[5];
  const float* bv  = (const float*)d_in[6];
  const float* Wsk = (const float*)d_in[7];
  const float* bsk = (const float*)d_in[8];
  float* out = (float*)d_out;

  split_w_kernel<<<(4 * WELEMS + 255) / 256, 256>>>(Wq, Wk, Wv, Wsk);

  cudaFuncSetAttribute(wg_kernel, cudaFuncAttributeMaxDynamicSharedMemorySize,
                       (int)SMEM_BYTES);
  wg_kernel<<<WB, NT, SMEM_BYTES>>>(x, bq, bk, bv, bsk, out);
}

// round 9
// speedup vs baseline: 1.4679x; 1.2875x over previous
#include <cuda_runtime.h>

// ---------------------------------------------------------------------------
// WindowGrapherPyg fused kernel, R8: barrier-free tensor-core GEMMs.
// W is pre-split (tf32 hi/lo, 3xTF32 compensation) AND pre-packed into
// per-lane mma fragment order in global memory (L2-resident, shared by all
// CTAs). GEMM inner loop: coalesced LDG.128 B fragments (double-buffered in
// registers) + A splits from smem + 18 MMAs per k-chunk. No __syncthreads
// and no smem staging inside the GEMMs.
// m16n8k8 fragment map (lane = 4*g+tig):
//   A: a0=(g,k=tig) a1=(g+8,tig) a2=(g,tig+4) a3=(g+8,tig+4)
//   B: b0=(k=tig,n=g) b1=(k=tig+4,n=g)
//   D: c0=(g,2tig) c1=(g,2tig+1) c2=(g+8,2tig) c3=(g+8,2tig+1)
// ---------------------------------------------------------------------------

typedef unsigned long long u64;

namespace {
constexpr int Bc = 2, Cc = 192, Hc = 192, Wc = 192;
constexpr int WS = 8, NN = 64, KK = 9, HEADS = 8, DH = 24;
constexpr int NWH = Hc / WS, NWW = Wc / WS;         // 24 x 24
constexpr int WB = Bc * NWH * NWW;                  // 1152 windows
constexpr int STR = 196;                            // xw/Q/K/V row stride
constexpr int NT = 512;
constexpr int XW_FLOATS = NN * STR;                 // 12544
constexpr int NTILES = Cc / 8;                      // 24 n-tiles
constexpr int KCH = Cc / 8;                         // 24 k-chunks
constexpr int FRAG_PER_MAT = NTILES * KCH * 32;     // 18432 float4
constexpr size_t SMEM_BYTES =
    (size_t)(4 * XW_FLOATS + NN * NN + NN) * sizeof(float) +
    (size_t)(NN * KK) * sizeof(int);                // 219,648 B
constexpr float INV_SQRT_DH = 0.20412414523193154f;
}

// Pre-packed tf32 hi/lo B fragments: [mat][ntile][kchunk][lane] float4.
__device__ float4 g_Wfrag[4 * FRAG_PER_MAT];

__device__ __forceinline__ u64 pack2f(float x, float y) {
  u64 r; asm("mov.b64 %0, {%1, %2};" : "=l"(r) : "f"(x), "f"(y)); return r;
}
__device__ __forceinline__ void fma2(u64& d, u64 a, u64 b) {
  asm("fma.rn.f32x2 %0, %1, %2, %0;" : "+l"(d) : "l"(a), "l"(b));
}
__device__ __forceinline__ float hsum2(u64 v) {
  float2 o; asm("mov.b64 {%0, %1}, %2;" : "=f"(o.x), "=f"(o.y) : "l"(v));
  return o.x + o.y;
}
__device__ __forceinline__ unsigned cvt_tf32(float f) {
  unsigned r; asm("cvt.rna.tf32.f32 %0, %1;" : "=r"(r) : "f"(f)); return r;
}
__device__ __forceinline__ void split_tf32(float f, unsigned& hi, unsigned& lo) {
  hi = cvt_tf32(f);
  lo = cvt_tf32(f - __uint_as_float(hi));
}
__device__ __forceinline__ void mma_tf32(float d[4], unsigned a0, unsigned a1,
                                         unsigned a2, unsigned a3,
                                         unsigned b0, unsigned b1) {
  asm("mma.sync.aligned.m16n8k8.row.col.f32.tf32.tf32.f32 "
      "{%0,%1,%2,%3}, {%4,%5,%6,%7}, {%8,%9}, {%0,%1,%2,%3};"
      : "+f"(d[0]), "+f"(d[1]), "+f"(d[2]), "+f"(d[3])
      : "r"(a0), "r"(a1), "r"(a2), "r"(a3), "r"(b0), "r"(b1));
}

// Prologue: pack W[k][n] (row-major KxN) into per-lane fragment float4s:
//   frag(mat, ntile, kc, lane) = {hi(W[k0][n]), hi(W[k0+4][n]),
//                                 lo(W[k0][n]), lo(W[k0+4][n])}
//   with n = ntile*8 + lane/4, k0 = kc*8 + lane%4.
__global__ void pack_w_kernel(const float* __restrict__ w0,
                              const float* __restrict__ w1,
                              const float* __restrict__ w2,
                              const float* __restrict__ w3) {
  int i = blockIdx.x * blockDim.x + threadIdx.x;
  if (i >= 4 * FRAG_PER_MAT) return;
  int lane = i & 31;
  int t = i >> 5;
  int kc = t % KCH; t /= KCH;
  int ntile = t % NTILES;
  int mat = t / NTILES;
  const float* W = (mat == 0) ? w0 : (mat == 1) ? w1 : (mat == 2) ? w2 : w3;
  int n = ntile * 8 + (lane >> 2);
  int k0 = kc * 8 + (lane & 3);
  unsigned h0, l0, h1, l1;
  split_tf32(W[k0 * Cc + n], h0, l0);
  split_tf32(W[(k0 + 4) * Cc + n], h1, l1);
  g_Wfrag[i] = make_float4(__uint_as_float(h0), __uint_as_float(h1),
                           __uint_as_float(l0), __uint_as_float(l1));
}

// Warp (16): mt = warp>>2 (16 rows), wg = warp&3 (48 cols = 6 n-tiles).
// acc[6][4]. Zero barriers; B double-buffered from global fragments.
__device__ __forceinline__ void gemm_core(const float* __restrict__ sXW,
                                          const float4* __restrict__ wf,
                                          float acc[6][4], int tid) {
  const int warp = tid >> 5, lane = tid & 31;
  const int g = lane >> 2, tig = lane & 3;
  const int mt = warp >> 2, wg = warp & 3;
  const int r0 = mt * 16 + g;
#pragma unroll
  for (int j = 0; j < 6; j++)
#pragma unroll
    for (int q = 0; q < 4; q++) acc[j][q] = 0.0f;

  // fragment base for this warp's 6 n-tiles
  const float4* wfb = wf + (wg * 6) * (KCH * 32) + lane;
  float4 bf[6];
#pragma unroll
  for (int j = 0; j < 6; j++) bf[j] = wfb[j * (KCH * 32)];

  const float* ap0 = sXW + r0 * STR + tig;
#pragma unroll 2
  for (int kc = 0; kc < KCH; kc++) {
    // A fragments for this k-chunk (k = kc*8 + tig, +4)
    const float* ap = ap0 + kc * 8;
    unsigned ah[4], al[4];
    split_tf32(ap[0],           ah[0], al[0]);
    split_tf32(ap[8 * STR],     ah[1], al[1]);
    split_tf32(ap[4],           ah[2], al[2]);
    split_tf32(ap[8 * STR + 4], ah[3], al[3]);
    float4 cur[6];
#pragma unroll
    for (int j = 0; j < 6; j++) cur[j] = bf[j];
    int kn = (kc + 1 < KCH) ? kc + 1 : 0;  // harmless wrap prefetch
#pragma unroll
    for (int j = 0; j < 6; j++) bf[j] = wfb[j * (KCH * 32) + kn * 32];
#pragma unroll
    for (int j = 0; j < 6; j++) {
      unsigned bh0 = __float_as_uint(cur[j].x);
      unsigned bh1 = __float_as_uint(cur[j].y);
      unsigned bl0 = __float_as_uint(cur[j].z);
      unsigned bl1 = __float_as_uint(cur[j].w);
      mma_tf32(acc[j], ah[0], ah[1], ah[2], ah[3], bh0, bh1);
      mma_tf32(acc[j], ah[0], ah[1], ah[2], ah[3], bl0, bl1);
      mma_tf32(acc[j], al[0], al[1], al[2], al[3], bh0, bh1);
    }
  }
}

__device__ __forceinline__ void gemm_to_smem(const float* __restrict__ sXW,
                                             const float4* __restrict__ wf,
                                             const float* __restrict__ bias,
                                             float* __restrict__ dst, int tid) {
  float acc[6][4];
  gemm_core(sXW, wf, acc, tid);
  const int warp = tid >> 5, lane = tid & 31;
  const int g = lane >> 2, tig = lane & 3;
  const int mt = warp >> 2, wg = warp & 3;
  const int r0 = mt * 16 + g;
#pragma unroll
  for (int j = 0; j < 6; j++) {
    const int c = wg * 48 + 8 * j + 2 * tig;
    float2 bj = *(const float2*)(bias + c);
    *(float2*)(dst + r0 * STR + c) =
        make_float2(acc[j][0] + bj.x, acc[j][1] + bj.y);
    *(float2*)(dst + (r0 + 8) * STR + c) =
        make_float2(acc[j][2] + bj.x, acc[j][3] + bj.y);
  }
}

__device__ __forceinline__ void gemm_skip_out(const float* __restrict__ sXW,
                                              const float4* __restrict__ wf,
                                              const float* __restrict__ bias,
                                              const float* __restrict__ sAttn,
                                              float* __restrict__ out,
                                              int b, int h0, int w0, int tid) {
  float acc[6][4];
  gemm_core(sXW, wf, acc, tid);
  const int warp = tid >> 5, lane = tid & 31;
  const int g = lane >> 2, tig = lane & 3;
  const int mt = warp >> 2, wg = warp & 3;
  const int r0 = mt * 16 + g;       // node (nh=2mt,   nw=g)
  const int r1 = r0 + 8;            // node (nh=2mt+1, nw=g)
  const long hw0 = (long)(h0 + 2 * mt) * Wc + w0 + g;
  const long hw1 = hw0 + Wc;
#pragma unroll
  for (int j = 0; j < 6; j++) {
    const int c = wg * 48 + 8 * j + 2 * tig;
    float2 bj = *(const float2*)(bias + c);
    float v00 = acc[j][0] + bj.x + sAttn[r0 * STR + c];
    float v01 = acc[j][1] + bj.y + sAttn[r0 * STR + c + 1];
    float v10 = acc[j][2] + bj.x + sAttn[r1 * STR + c];
    float v11 = acc[j][3] + bj.y + sAttn[r1 * STR + c + 1];
    float* base0 = out + (long)(b * Cc + c) * Hc * Wc;
    float* base1 = out + (long)(b * Cc + c + 1) * Hc * Wc;
    base0[hw0] = v00; base1[hw0] = v01;
    base0[hw1] = v10; base1[hw1] = v11;
  }
}

__global__ void __launch_bounds__(NT, 1)
wg_kernel(const float* __restrict__ x,
          const float* __restrict__ bq, const float* __restrict__ bk,
          const float* __restrict__ bv, const float* __restrict__ bsk,
          float* __restrict__ out) {
  extern __shared__ float sm[];
  float* sXW = sm;
  float* sQ = sXW + XW_FLOATS;
  float* sK = sQ + XW_FLOATS;
  float* sV = sK + XW_FLOATS;
  float* sG = sV + XW_FLOATS;    // 4096 floats
  float* sSq = sG + NN * NN;     // 64 floats
  int* sIdx = (int*)(sSq + NN);  // 64*9 ints

  const int tid = threadIdx.x;
  const int w = blockIdx.x;
  const int b = w / (NWH * NWW);
  const int rem = w - b * (NWH * NWW);
  const int wh = rem / NWW, ww = rem - wh * NWW;
  const int h0 = wh * WS, w0 = ww * WS;

  // ---- Phase A: gather window nodes ----
#pragma unroll
  for (int i = 0; i < 3; i++) {
    int t = tid + NT * i;          // 0..1535 : (c, nh)
    int c = t >> 3, nh = t & 7;
    const float* src = x + ((b * Cc + c) * Hc + h0 + nh) * Wc + w0;
    float4 v0 = *(const float4*)src;
    float4 v1 = *(const float4*)(src + 4);
    float* d = sXW + (nh * 8) * STR + c;
    d[0 * STR] = v0.x; d[1 * STR] = v0.y; d[2 * STR] = v0.z; d[3 * STR] = v0.w;
    d[4 * STR] = v1.x; d[5 * STR] = v1.y; d[6 * STR] = v1.z; d[7 * STR] = v1.w;
  }
  __syncthreads();

  // ---- Phase B1: Gram matrix (exact fp32), 1 row x 8 cols per thread ----
  {
    const int tn = tid >> 3;        // 0..63 (row)
    const int tm8 = tid & 7;        // cols tm8 + 8j
    u64 acc2[8];
#pragma unroll
    for (int j = 0; j < 8; j++) acc2[j] = 0ull;
    const float* ar = sXW + tn * STR;
#pragma unroll 2
    for (int k = 0; k < Cc; k += 4) {
      float4 a = *(const float4*)(ar + k);
      u64 alo = pack2f(a.x, a.y), ahi = pack2f(a.z, a.w);
#pragma unroll
      for (int j = 0; j < 8; j++) {
        float4 bb = *(const float4*)(sXW + (tm8 + 8 * j) * STR + k);
        fma2(acc2[j], alo, pack2f(bb.x, bb.y));
        fma2(acc2[j], ahi, pack2f(bb.z, bb.w));
      }
    }
#pragma unroll
    for (int j = 0; j < 8; j++)
      sG[tn * NN + tm8 + 8 * j] = hsum2(acc2[j]);
  }
  __syncthreads();
  if (tid < NN) sSq[tid] = sG[tid * (NN + 1)];
  __syncthreads();

  // ---- Phase B2: top-9 nearest neighbors (stable, exact fp32) ----
  if (tid < NN) {
    const int n = tid;
    unsigned long long mask = 1ull << n;  // exclude self
    const float sqn = sSq[n];
    const float* grow = sG + n * NN;
#pragma unroll 1
    for (int kk = 0; kk < KK; kk++) {
      float best = 3.0e38f;
      int bi = 0;
#pragma unroll 4
      for (int m = 0; m < NN; m++) {
        float d = sqn + sSq[m] - 2.0f * grow[m];
        if ((mask >> m) & 1ull) d = 3.9e38f;
        if (d < best) { best = d; bi = m; }  // '<' = lowest index wins ties
      }
      mask |= 1ull << bi;
      sIdx[n * KK + kk] = bi;
    }
  }

  // ---- Phase C: Q, K, V projections (tensor core, barrier-free) ----
  gemm_to_smem(sXW, g_Wfrag + 0 * FRAG_PER_MAT, bq, sQ, tid);
  gemm_to_smem(sXW, g_Wfrag + 1 * FRAG_PER_MAT, bk, sK, tid);
  gemm_to_smem(sXW, g_Wfrag + 2 * FRAG_PER_MAT, bv, sV, tid);
  __syncthreads();  // sQ/sK/sV (and sIdx) visible before attention

  // ---- Phase D: 9-neighbor softmax attention; 512 thr = one (n,h) each ----
  {
    const int n = tid & (NN - 1);
    const int h = tid >> 6;
    const float* qp = sQ + n * STR + h * DH;
    float q[DH];
#pragma unroll
    for (int d4 = 0; d4 < DH / 4; d4++) {
      float4 v = *(const float4*)(qp + d4 * 4);
      q[d4 * 4 + 0] = v.x; q[d4 * 4 + 1] = v.y;
      q[d4 * 4 + 2] = v.z; q[d4 * 4 + 3] = v.w;
    }
    float sc[KK];
    int nb[KK];
#pragma unroll
    for (int kk = 0; kk < KK; kk++) {
      int m = sIdx[n * KK + kk];
      nb[kk] = m;
      const float* kp = sK + m * STR + h * DH;
      float s = 0.0f;
#pragma unroll
      for (int d4 = 0; d4 < DH / 4; d4++) {
        float4 v = *(const float4*)(kp + d4 * 4);
        s = fmaf(q[d4 * 4 + 0], v.x, s);
        s = fmaf(q[d4 * 4 + 1], v.y, s);
        s = fmaf(q[d4 * 4 + 2], v.z, s);
        s = fmaf(q[d4 * 4 + 3], v.w, s);
      }
      sc[kk] = s * INV_SQRT_DH;
    }
    float mx = sc[0];
#pragma unroll
    for (int kk = 1; kk < KK; kk++) mx = fmaxf(mx, sc[kk]);
    float ssum = 0.0f;
#pragma unroll
    for (int kk = 0; kk < KK; kk++) { sc[kk] = __expf(sc[kk] - mx); ssum += sc[kk]; }
    const float inv = 1.0f / ssum;
    float o[DH] = {};
#pragma unroll
    for (int kk = 0; kk < KK; kk++) {
      float a = sc[kk] * inv;
      const float* vp = sV + nb[kk] * STR + h * DH;
#pragma unroll
      for (int d4 = 0; d4 < DH / 4; d4++) {
        float4 v = *(const float4*)(vp + d4 * 4);
        o[d4 * 4 + 0] = fmaf(a, v.x, o[d4 * 4 + 0]);
        o[d4 * 4 + 1] = fmaf(a, v.y, o[d4 * 4 + 1]);
        o[d4 * 4 + 2] = fmaf(a, v.z, o[d4 * 4 + 2]);
        o[d4 * 4 + 3] = fmaf(a, v.w, o[d4 * 4 + 3]);
      }
    }
    float* op = sQ + n * STR + h * DH;  // attn out overwrites own q segment
#pragma unroll
    for (int d4 = 0; d4 < DH / 4; d4++)
      *(float4*)(op + d4 * 4) =
          make_float4(o[d4 * 4 + 0], o[d4 * 4 + 1], o[d4 * 4 + 2], o[d4 * 4 + 3]);
  }
  __syncthreads();  // attn results in sQ visible before skip epilogue reads

  // ---- Phase E: skip GEMM + attn add + scatter to [B,C,H,W] ----
  gemm_skip_out(sXW, g_Wfrag + 3 * FRAG_PER_MAT, bsk, sQ, out, b, h0, w0, tid);
}

extern "C" void kernel_launch(void* const* d_in, const int* in_sizes, int n_in,
                              void* d_out, int out_size) {
  const float* x   = (const float*)d_in[0];
  const float* Wq  = (const float*)d_in[1];
  const float* bq  = (const float*)d_in[2];
  const float* Wk  = (const float*)d_in[3];
  const float* bk  = (const float*)d_in[4];
  const float* Wv  = (const float*)d_in[5];
  const float* bv  = (const float*)d_in[6];
  const float* Wsk = (const float*)d_in[7];
  const float* bsk = (const float*)d_in[8];
  float* out = (float*)d_out;

  pack_w_kernel<<<(4 * FRAG_PER_MAT + 255) / 256, 256>>>(Wq, Wk, Wv, Wsk);

  cudaFuncSetAttribute(wg_kernel, cudaFuncAttributeMaxDynamicSharedMemorySize,
                       (int)SMEM_BYTES);
  wg_kernel<<<WB, NT, SMEM_BYTES>>>(x, bq, bk, bv, bsk, out);
}